// round 16
// baseline (speedup 1.0000x reference)
#include <cuda_runtime.h>
#include <cuda_fp16.h>
#include <cstdint>

#define EPSF 1e-5f

// ---------------- scratch (static device globals; no allocation) ----------------
__device__ __half g_xh[(size_t)1024 * 49 * 512];    // fp16 input
__device__ __half g_h[(size_t)4 * 21504 * 512];     // region GEMM out; activated fp16 in place
__device__ __half g_y[(size_t)12 * 21504 * 512];    // class GEMM out (pre-BN, fp16)
__device__ __half g_wt[(size_t)17 * 512 * 512];     // fragment-packed fp16 weights
__device__ __half g_hg[(size_t)1024 * 12 * 512];    // GAT projection (fp16)
__device__ __half g_fvh[(size_t)1024 * 12 * 512];   // f_v fp16 (GEMM operand)
__device__ float g_hmean[(size_t)4 * 1024 * 512];   // seq-mean of activated h
__device__ float g_fv[(size_t)1024 * 12 * 512];     // f_v fp32 (GAT residual)
__device__ float g_gat[(size_t)1024 * 12 * 512];    // GAT output
__device__ float g_v[(size_t)1024 * 12 * 512];      // temporal conv out (pre-BN)
__device__ float g_rstats[4 * 512 * 2];
__device__ float g_cstats[12 * 512 * 2];
__device__ float g_tstats[24];

__constant__ int c_sel[12]  = {0, 0, 0, 1, 0, 3, 2, 2, 2, 3, 3, 3};
__constant__ int c_start[4] = {0, 14, 28, 28};
__constant__ float c_adj[144] = {
    0,0,0,1,0,1,1,1,1,1,1,1,
    0,0,0,1,0,1,1,1,1,1,1,1,
    0,0,0,1,0,1,1,1,1,1,1,1,
    1,1,1,0,1,1,1,1,1,1,1,1,
    0,0,0,1,0,1,1,1,1,1,1,1,
    1,1,1,1,1,0,1,1,1,0,0,0,
    1,1,1,1,1,1,0,0,0,1,1,1,
    1,1,1,1,1,1,0,0,0,1,1,1,
    1,1,1,1,1,1,0,0,0,1,1,1,
    1,1,1,1,1,0,1,1,1,0,0,0,
    1,1,1,1,1,0,1,1,1,0,0,0,
    1,1,1,1,1,0,1,1,1,0,0,0
};

// ---------------- helpers ----------------
__device__ __forceinline__ uint32_t smem_u32(const void* p) {
    uint32_t a;
    asm("{ .reg .u64 t; cvta.to.shared.u64 t, %1; cvt.u32.u64 %0, t; }" : "=r"(a) : "l"(p));
    return a;
}
__device__ __forceinline__ uint32_t f2h2(float a, float b) {
    __half2 h = __floats2half2_rn(a, b);
    return *(uint32_t*)&h;
}
#define CP_ASYNC16(dst, src) \
    asm volatile("cp.async.ca.shared.global [%0], [%1], 16;" :: "r"(dst), "l"(src) : "memory")
#define CP_COMMIT() asm volatile("cp.async.commit_group;" ::: "memory")
#define CP_WAIT0()  asm volatile("cp.async.wait_group 0;" ::: "memory")
#define CP_WAIT1()  asm volatile("cp.async.wait_group 1;" ::: "memory")

#define LDSM_X4(r0, r1, r2, r3, addr) \
    asm volatile("ldmatrix.sync.aligned.m8n8.x4.shared.b16 {%0,%1,%2,%3}, [%4];" \
        : "=r"(r0), "=r"(r1), "=r"(r2), "=r"(r3) : "r"(addr))

#define MMA_F16(D, A, B0, B1) \
    asm volatile("mma.sync.aligned.m16n8k16.row.col.f32.f16.f16.f32 " \
        "{%0,%1,%2,%3}, {%4,%5,%6,%7}, {%8,%9}, {%0,%1,%2,%3};" \
        : "+f"((D)[0]), "+f"((D)[1]), "+f"((D)[2]), "+f"((D)[3]) \
        : "r"((A)[0]), "r"((A)[1]), "r"((A)[2]), "r"((A)[3]), \
          "r"(B0), "r"(B1))

// ---------------- prep: x -> fp16, zero stats ----------------
__global__ void prep_kernel(const float* __restrict__ x) {
    size_t base = ((size_t)blockIdx.x * 256 + threadIdx.x) * 8;
    float4 f0 = *(const float4*)(x + base);
    float4 f1 = *(const float4*)(x + base + 4);
    uint4 u;
    u.x = f2h2(f0.x, f0.y); u.y = f2h2(f0.z, f0.w);
    u.z = f2h2(f1.x, f1.y); u.w = f2h2(f1.z, f1.w);
    *(uint4*)(g_xh + base) = u;
    if (blockIdx.x == 0) {
        for (int j = threadIdx.x; j < 4 * 512 * 2; j += 256)  g_rstats[j] = 0.f;
        for (int j = threadIdx.x; j < 12 * 512 * 2; j += 256) g_cstats[j] = 0.f;
        if (threadIdx.x < 24) g_tstats[threadIdx.x] = 0.f;
    }
}

// ---------------- weight fragment-pack to fp16 ----------------
// layout per z: [ntile 4][kbg 32][p 8][256 halfs in m16n8k16-B fragment order]
__global__ void pack_wt(const float* __restrict__ rW,
                        const float* __restrict__ cW,
                        const float* __restrict__ gW, int z0) {
    __shared__ float tile[16][17];
    const int z = blockIdx.z + z0;
    const int npg = blockIdx.y;
    const int kbg = blockIdx.x;
    const float* src = (z < 4) ? rW + (size_t)z * 262144
                     : (z < 16) ? cW + (size_t)(z - 4) * 262144 : gW;
    const int i = threadIdx.x;
    {
        int k_l = i >> 4, n_l = i & 15;
        tile[k_l][n_l] = src[(size_t)(kbg * 16 + k_l) * 512 + npg * 16 + n_l];
    }
    __syncthreads();
    const int l = i >> 3, rem = i & 7;
    const int sub = rem >> 2, reg = (rem >> 1) & 1, hi = rem & 1;
    const int g = l >> 2, t = l & 3;
    const int k_l = reg * 8 + t * 2 + hi;
    const int n_l = sub * 8 + g;
    const int ntile = npg >> 3, p = npg & 7;
    size_t dst = ((((size_t)z * 4 + ntile) * 32 + kbg) * 8 + p) * 256 + i;
    g_wt[dst] = __float2half_rn(tile[k_l][n_l]);
}

// ====== fp16 mma.sync GEMM: block 128x128, 4 warps x (64x64), KC=32, 3-stage, ldmatrix A ======
// SMEM: A 3x10240 at 0; B 3x8192 at 30720; epilogue stage [128][136] halfs reuses from 0.
#define SMEM_DYN 55296
__global__ void __launch_bounds__(128, 3) gemm_h(const float* __restrict__ bias, int M, int mode)
{
    extern __shared__ char smc[];
    __half* stg = (__half*)smc;
    __shared__ float s_bias[128], s_cs1[128], s_cs2[128];

    const int tid = threadIdx.x;
    const int w = tid >> 5, l = tid & 31;
    const int wm = w >> 1, wn = w & 1;      // warp tile: rows wm*64, cols wn*64
    const int g = l >> 2, t = l & 3;
    const int z = blockIdx.z;
    const int ntile = blockIdx.x;
    const int n0 = ntile * 128;
    const int m0 = blockIdx.y * 128;

    __half* Y;
    int sel = 0;
    if (mode == 0)      { Y = g_h; }
    else if (mode == 1) { Y = g_y; sel = c_sel[z]; }
    else                { Y = g_hg; }

    s_bias[tid] = bias ? bias[(size_t)z * 512 + n0 + tid] : 0.f;
    s_cs1[tid] = 0.f;
    s_cs2[tid] = 0.f;

    // A loader: thread = one row (0..127), 64B per stage
    const __half* arow;
    {
        int m = m0 + tid;
        if (mode == 0) {
            int bt = m / 21, s = m - bt * 21;
            arow = g_xh + ((size_t)bt * 49 + c_start[z] + s) * 512;
        } else if (mode == 1) {
            arow = g_h + ((size_t)sel * 21504 + m) * 512;
        } else {
            arow = g_fvh + (size_t)m * 512;
        }
    }
    const int zw = (mode == 0) ? z : (mode == 1) ? 4 + z : 16;
    const char* gB = (const char*)g_wt + (size_t)zw * 524288 + (size_t)ntile * 131072;
    const uint32_t sBase = smem_u32(smc);
    const uint32_t adst = sBase + tid * 80;
    const uint32_t bdst = sBase + 30720 + tid * 16;
    // ldmatrix lane address: row = warp row base + (l&15), k-byte = (l>>4)*16
    const uint32_t a_lm = sBase + (wm * 64 + (l & 15)) * 80 + (l >> 4) * 16;

    float d[4][8][4];
    #pragma unroll
    for (int mf = 0; mf < 4; ++mf)
        #pragma unroll
        for (int nf = 0; nf < 8; ++nf)
            #pragma unroll
            for (int q = 0; q < 4; ++q) d[mf][nf][q] = 0.f;

    auto loadAB = [&](int kt, int bf) {
        const char* as = (const char*)(arow + kt * 32);
        uint32_t ad = adst + bf * 10240;
        #pragma unroll
        for (int i = 0; i < 4; ++i)
            CP_ASYNC16(ad + i * 16, as + i * 16);
        const char* bs = gB + (size_t)kt * 8192 + tid * 16;
        uint32_t bd = bdst + bf * 8192;
        #pragma unroll
        for (int i = 0; i < 4; ++i)
            CP_ASYNC16(bd + i * 2048, bs + i * 2048);
        CP_COMMIT();
    };

    // prologue: stages 0,1 in flight
    loadAB(0, 0);
    loadAB(1, 1);
    CP_WAIT1();
    __syncthreads();

    for (int kt = 0; kt < 16; ++kt) {
        const int buf = kt - (kt / 3) * 3;   // kt % 3
        if (kt + 2 < 16) {
            int nb = (kt + 2) - ((kt + 2) / 3) * 3;
            loadAB(kt + 2, nb);
        }
        const char* Bb = smc + 30720 + buf * 8192;
        const uint32_t ab = a_lm + buf * 10240;
        #pragma unroll
        for (int kb2 = 0; kb2 < 2; ++kb2) {
            uint32_t af[4][4];
            #pragma unroll
            for (int mf = 0; mf < 4; ++mf)
                LDSM_X4(af[mf][0], af[mf][1], af[mf][2], af[mf][3],
                        ab + mf * 16 * 80 + kb2 * 32);
            #pragma unroll
            for (int jh = 0; jh < 2; ++jh) {
                uint4 bv0 = *(const uint4*)(Bb + ((kb2 * 8 + wn * 4 + jh * 2) * 32 + l) * 16);
                uint4 bv1 = *(const uint4*)(Bb + ((kb2 * 8 + wn * 4 + jh * 2 + 1) * 32 + l) * 16);
                #pragma unroll
                for (int mf = 0; mf < 4; ++mf) {
                    MMA_F16(d[mf][jh * 4 + 0], af[mf], bv0.x, bv0.y);
                    MMA_F16(d[mf][jh * 4 + 1], af[mf], bv0.z, bv0.w);
                    MMA_F16(d[mf][jh * 4 + 2], af[mf], bv1.x, bv1.y);
                    MMA_F16(d[mf][jh * 4 + 3], af[mf], bv1.z, bv1.w);
                }
            }
        }
        if (kt < 15) {
            if (kt + 2 < 16) { CP_WAIT1(); } else { CP_WAIT0(); }
        }
        __syncthreads();
    }

    // ---- epilogue: single pass, half stage, fp32 stats ----
    {
        float cs[16], cq[16];
        #pragma unroll
        for (int i = 0; i < 16; ++i) { cs[i] = 0.f; cq[i] = 0.f; }
        #pragma unroll
        for (int mf = 0; mf < 4; ++mf) {
            #pragma unroll
            for (int nf = 0; nf < 8; ++nf) {
                int col = wn * 64 + nf * 8 + 2 * t;
                float b0 = s_bias[col], b1 = s_bias[col + 1];
                int r0 = wm * 64 + mf * 16 + g;
                float v00 = d[mf][nf][0] + b0;
                float v01 = d[mf][nf][1] + b1;
                float v10 = d[mf][nf][2] + b0;
                float v11 = d[mf][nf][3] + b1;
                *(__half2*)&stg[r0 * 136 + col]       = __floats2half2_rn(v00, v01);
                *(__half2*)&stg[(r0 + 8) * 136 + col] = __floats2half2_rn(v10, v11);
                cs[nf * 2]     += v00 + v10;
                cq[nf * 2]     += v00 * v00 + v10 * v10;
                cs[nf * 2 + 1] += v01 + v11;
                cq[nf * 2 + 1] += v01 * v01 + v11 * v11;
            }
        }
        if (mode != 2) {
            #pragma unroll
            for (int i = 0; i < 16; ++i) {
                #pragma unroll
                for (int msk = 4; msk <= 16; msk <<= 1) {
                    cs[i] += __shfl_xor_sync(0xFFFFFFFFu, cs[i], msk);
                    cq[i] += __shfl_xor_sync(0xFFFFFFFFu, cq[i], msk);
                }
            }
            if (l < 4) {
                #pragma unroll
                for (int nf = 0; nf < 8; ++nf) {
                    int col = wn * 64 + nf * 8 + 2 * l;
                    atomicAdd(&s_cs1[col],     cs[nf * 2]);
                    atomicAdd(&s_cs2[col],     cq[nf * 2]);
                    atomicAdd(&s_cs1[col + 1], cs[nf * 2 + 1]);
                    atomicAdd(&s_cs2[col + 1], cq[nf * 2 + 1]);
                }
            }
        }
    }
    __syncthreads();
    {
        __half* yrow = Y + ((size_t)z * M + m0 + tid) * 512 + n0;
        const __half* srow = stg + tid * 136;
        #pragma unroll
        for (int q = 0; q < 16; ++q)
            *(uint4*)(yrow + q * 8) = *(const uint4*)(srow + q * 8);
    }
    if (mode != 2) {
        float* stats = (mode == 0) ? g_rstats : g_cstats;
        atomicAdd(&stats[((size_t)z * 512 + n0 + tid) * 2],     s_cs1[tid]);
        atomicAdd(&stats[((size_t)z * 512 + n0 + tid) * 2 + 1], s_cs2[tid]);
    }
}

// ---------------- hmean: finalize region BN, activate g_h IN PLACE (fp16), seq-mean ----------------
__global__ void hmean_kernel(const float* __restrict__ gamma, const float* __restrict__ beta) {
    const int bt = blockIdx.x, r = blockIdx.y;
    const int c = threadIdx.x * 8;
    float sc[8], sh[8];
    #pragma unroll
    for (int j = 0; j < 8; ++j) {
        int i = r * 512 + c + j;
        float mean = g_rstats[i * 2] * (1.f / 21504.f);
        float var  = g_rstats[i * 2 + 1] * (1.f / 21504.f) - mean * mean;
        float rstd = rsqrtf(var + EPSF);
        sc[j] = gamma[i] * rstd;
        sh[j] = beta[i] - mean * sc[j];
    }
    size_t base = ((size_t)r * 21504 + (size_t)bt * 21) * 512 + c;
    float acc[8] = {0.f, 0.f, 0.f, 0.f, 0.f, 0.f, 0.f, 0.f};
    #pragma unroll
    for (int s = 0; s < 21; ++s) {
        uint4 u = *(const uint4*)(g_h + base + (size_t)s * 512);
        const __half2* hp = (const __half2*)&u;
        float av[8];
        #pragma unroll
        for (int p = 0; p < 4; ++p) {
            float2 f = __half22float2(hp[p]);
            av[p * 2]     = fmaxf(fmaf(f.x, sc[p * 2],     sh[p * 2]),     0.f);
            av[p * 2 + 1] = fmaxf(fmaf(f.y, sc[p * 2 + 1], sh[p * 2 + 1]), 0.f);
            acc[p * 2]     += av[p * 2];
            acc[p * 2 + 1] += av[p * 2 + 1];
        }
        uint4 o;
        o.x = f2h2(av[0], av[1]); o.y = f2h2(av[2], av[3]);
        o.z = f2h2(av[4], av[5]); o.w = f2h2(av[6], av[7]);
        *(uint4*)(g_h + base + (size_t)s * 512) = o;
    }
    float* dst = g_hmean + ((size_t)r * 1024 + bt) * 512 + c;
    #pragma unroll
    for (int j = 0; j < 8; ++j) dst[j] = acc[j] * (1.f / 21.f);
}

// ---------------- BN+ReLU on y + seq-mean -> f_v (fp32 + fp16) ----------------
__global__ void bn_y_kernel(const float* __restrict__ gamma, const float* __restrict__ beta) {
    const int bt = blockIdx.x, n = blockIdx.y;
    const int c = threadIdx.x * 8;
    float sc[8], sh[8];
    #pragma unroll
    for (int j = 0; j < 8; ++j) {
        int i = n * 512 + c + j;
        float mean = g_cstats[i * 2] * (1.f / 21504.f);
        float var  = g_cstats[i * 2 + 1] * (1.f / 21504.f) - mean * mean;
        float rstd = rsqrtf(var + EPSF);
        sc[j] = gamma[i] * rstd;
        sh[j] = beta[i] - mean * sc[j];
    }
    size_t base = ((size_t)n * 21504 + (size_t)bt * 21) * 512 + c;
    float acc[8] = {0.f, 0.f, 0.f, 0.f, 0.f, 0.f, 0.f, 0.f};
    #pragma unroll
    for (int s = 0; s < 21; ++s) {
        uint4 u = *(const uint4*)(g_y + base + (size_t)s * 512);
        const __half2* hp = (const __half2*)&u;
        #pragma unroll
        for (int p = 0; p < 4; ++p) {
            float2 f = __half22float2(hp[p]);
            acc[p * 2]     += fmaxf(fmaf(f.x, sc[p * 2],     sh[p * 2]),     0.f);
            acc[p * 2 + 1] += fmaxf(fmaf(f.y, sc[p * 2 + 1], sh[p * 2 + 1]), 0.f);
        }
    }
    size_t didx = ((size_t)bt * 12 + n) * 512 + c;
    float* dst = g_fv + didx;
    #pragma unroll
    for (int j = 0; j < 8; ++j) {
        acc[j] *= (1.f / 21.f);
        dst[j] = acc[j];
    }
    uint4 o;
    o.x = f2h2(acc[0], acc[1]); o.y = f2h2(acc[2], acc[3]);
    o.z = f2h2(acc[4], acc[5]); o.w = f2h2(acc[6], acc[7]);
    *(uint4*)(g_fvh + didx) = o;
}

// ---------------- prediction heads ----------------
__global__ void preds_kernel(const float* __restrict__ upW,  const float* __restrict__ upb,
                             const float* __restrict__ midW, const float* __restrict__ midb,
                             const float* __restrict__ d1W,  const float* __restrict__ d1b,
                             const float* __restrict__ d2W,  const float* __restrict__ d2b,
                             float* __restrict__ out)
{
    __shared__ float smh[2048];
    const int bt = blockIdx.x;
    for (int i = threadIdx.x; i < 2048; i += 256)
        smh[i] = g_hmean[((size_t)(i >> 9) * 1024 + bt) * 512 + (i & 511)];
    __syncthreads();
    const int w = threadIdx.x >> 5, l = threadIdx.x & 31;
    for (int o = w; o < 42; o += 8) {
        int r, j, nout;
        const float* Wp;
        const float* bp;
        float* op;
        if (o < 16)      { r = 0; j = o;      Wp = upW;  bp = upb;  op = out + (size_t)bt * 16;         nout = 16; }
        else if (o < 18) { r = 1; j = o - 16; Wp = midW; bp = midb; op = out + 16384 + (size_t)bt * 2;  nout = 2;  }
        else if (o < 26) { r = 2; j = o - 18; Wp = d1W;  bp = d1b;  op = out + 18432 + (size_t)bt * 8;  nout = 8;  }
        else             { r = 3; j = o - 26; Wp = d2W;  bp = d2b;  op = out + 26624 + (size_t)bt * 16; nout = 16; }
        float a = 0.f;
        for (int c = l; c < 512; c += 32) a += smh[r * 512 + c] * Wp[c * nout + j];
        #pragma unroll
        for (int off = 16; off; off >>= 1) a += __shfl_xor_sync(0xFFFFFFFFu, a, off);
        if (l == 0) op[j] = a + bp[j];
    }
}

// ---------------- GAT (fp16 hg read, half2 loads) ----------------
__global__ void gat_kernel(const float* __restrict__ adj_mask,
                           const float* __restrict__ al,
                           const float* __restrict__ ar)
{
    __shared__ float hs[12 * 512];
    __shared__ float alp[12], arp[12];
    __shared__ float att[144];
    const int bt = blockIdx.x;
    const __half2* hgb = (const __half2*)(g_hg + (size_t)bt * 12 * 512);
    for (int i = threadIdx.x; i < 3072; i += 256) {
        float2 f = __half22float2(hgb[i]);
        hs[i * 2] = f.x;
        hs[i * 2 + 1] = f.y;
    }
    __syncthreads();
    const int w = threadIdx.x >> 5, lane = threadIdx.x & 31;
    for (int dd = w; dd < 24; dd += 8) {
        int node = dd >> 1;
        const float* vec = (dd & 1) ? ar : al;
        float s = 0.f;
        for (int c = lane; c < 512; c += 32) s += hs[node * 512 + c] * vec[c];
        #pragma unroll
        for (int o = 16; o; o >>= 1) s += __shfl_xor_sync(0xFFFFFFFFu, s, o);
        if (lane == 0) { if (dd & 1) arp[node] = s; else alp[node] = s; }
    }
    __syncthreads();
    if (threadIdx.x < 144) {
        int i = threadIdx.x / 12, j = threadIdx.x % 12;
        float a = c_adj[threadIdx.x] * adj_mask[(size_t)bt * 144 + threadIdx.x] + (i == j ? 1.f : 0.f);
        float e = alp[i] + arp[j];
        e = (e > 0.f) ? e : 0.2f * e;
        att[threadIdx.x] = (a > 0.1f) ? e : -1e9f;
    }
    __syncthreads();
    if (threadIdx.x < 12) {
        int i = threadIdx.x;
        float mx = -1e30f;
        for (int j = 0; j < 12; ++j) mx = fmaxf(mx, att[i * 12 + j]);
        float tmp[12];
        float sum = 0.f;
        for (int j = 0; j < 12; ++j) { float ev = expf(att[i * 12 + j] - mx); tmp[j] = ev; sum += ev; }
        float invs = 1.f / sum;
        for (int j = 0; j < 12; ++j) att[i * 12 + j] = tmp[j] * invs;
    }
    __syncthreads();
    const float* fvb = g_fv + (size_t)bt * 12 * 512;
    float* gb = g_gat + (size_t)bt * 12 * 512;
    for (int idx = threadIdx.x; idx < 6144; idx += 256) {
        int n = idx >> 9, c = idx & 511;
        float s = fvb[idx];
        #pragma unroll
        for (int j = 0; j < 12; ++j) s += att[n * 12 + j] * hs[j * 512 + c];
        gb[idx] = s;
    }
}

// ---------------- temporal conv, register sliding window, + BN stats ----------------
__global__ void tconv_kernel(const float* __restrict__ W, const float* __restrict__ bias) {
    const int b = blockIdx.x, n = blockIdx.y;
    const int c = threadIdx.x;
    float in[32];
    #pragma unroll
    for (int t = 0; t < 32; ++t)
        in[t] = g_gat[(((size_t)(b * 32 + t)) * 12 + n) * 512 + c];
    const float* wp = W + ((size_t)n * 512 + c) * 5;
    float w0 = wp[0], w1 = wp[1], w2 = wp[2], w3 = wp[3], w4 = wp[4];
    const float bv = bias[n * 512 + c];
    float s = 0.f, s2 = 0.f;
    #pragma unroll
    for (int t = 0; t < 32; ++t) {
        float v = bv;
        if (t >= 2)      v = fmaf(in[t - 2], w0, v);
        if (t >= 1)      v = fmaf(in[t - 1], w1, v);
        v = fmaf(in[t], w2, v);
        if (t + 1 < 32)  v = fmaf(in[t + 1], w3, v);
        if (t + 2 < 32)  v = fmaf(in[t + 2], w4, v);
        g_v[(((size_t)(b * 32 + t)) * 12 + n) * 512 + c] = v;
        s += v;
        s2 = fmaf(v, v, s2);
    }
    #pragma unroll
    for (int o = 16; o; o >>= 1) {
        s  += __shfl_xor_sync(0xFFFFFFFFu, s, o);
        s2 += __shfl_xor_sync(0xFFFFFFFFu, s2, o);
    }
    __shared__ float wsum[16], wsq[16];
    const int lane = c & 31, wrp = c >> 5;
    if (lane == 0) { wsum[wrp] = s; wsq[wrp] = s2; }
    __syncthreads();
    if (c == 0) {
        float a = 0.f, b2 = 0.f;
        #pragma unroll
        for (int i = 0; i < 16; ++i) { a += wsum[i]; b2 += wsq[i]; }
        atomicAdd(&g_tstats[n * 2],     a);
        atomicAdd(&g_tstats[n * 2 + 1], b2);
    }
}

// ---------------- final per-class BN + ReLU (float4) ----------------
__global__ void tbn_kernel(const float* __restrict__ gamma, const float* __restrict__ beta,
                           float* __restrict__ out) {
    const int bt = blockIdx.x, n = blockIdx.y;
    const int c = threadIdx.x * 4;
    const float cnt = 1.f / (1024.f * 512.f);
    const float mean = g_tstats[n * 2] * cnt;
    const float var  = g_tstats[n * 2 + 1] * cnt - mean * mean;
    const float rstd = rsqrtf(var + EPSF);
    const float sc = gamma[n] * rstd;
    const float sh = beta[n] - mean * sc;
    size_t idx = ((size_t)bt * 12 + n) * 512 + c;
    float4 v = *(const float4*)(g_v + idx);
    v.x = fmaxf(fmaf(v.x, sc, sh), 0.f);
    v.y = fmaxf(fmaf(v.y, sc, sh), 0.f);
    v.z = fmaxf(fmaf(v.z, sc, sh), 0.f);
    v.w = fmaxf(fmaf(v.w, sc, sh), 0.f);
    *(float4*)(out + 43008 + idx) = v;
}

// ---------------- launch (fork/join on side streams) ----------------
extern "C" void kernel_launch(void* const* d_in, const int* in_sizes, int n_in,
                              void* d_out, int out_size)
{
    const float* x            = (const float*)d_in[0];
    const float* adj_mask     = (const float*)d_in[1];
    const float* region_W     = (const float*)d_in[2];
    const float* region_b     = (const float*)d_in[3];
    const float* region_gamma = (const float*)d_in[4];
    const float* region_beta  = (const float*)d_in[5];
    const float* upfc_W  = (const float*)d_in[6];
    const float* upfc_b  = (const float*)d_in[7];
    const float* midfc_W = (const float*)d_in[8];
    const float* midfc_b = (const float*)d_in[9];
    const float* d1fc_W  = (const float*)d_in[10];
    const float* d1fc_b  = (const float*)d_in[11];
    const float* d2fc_W  = (const float*)d_in[12];
    const float* d2fc_b  = (const float*)d_in[13];
    const float* class_W     = (const float*)d_in[14];
    const float* class_b     = (const float*)d_in[15];
    const float* class_gamma = (const float*)d_in[16];
    const float* class_beta  = (const float*)d_in[17];
    const float* gat_W  = (const float*)d_in[18];
    const float* gat_al = (const float*)d_in[19];
    const float* gat_ar = (const float*)d_in[20];
    const float* tconv_W   = (const float*)d_in[21];
    const float* tconv_b   = (const float*)d_in[22];
    const float* tbn_gamma = (const float*)d_in[23];
    const float* tbn_beta  = (const float*)d_in[24];
    float* out = (float*)d_out;

    cudaFuncSetAttribute(gemm_h, cudaFuncAttributeMaxDynamicSharedMemorySize, SMEM_DYN);

    cudaStream_t sd1, sd2;
    cudaStreamCreateWithFlags(&sd1, cudaStreamNonBlocking);
    cudaStreamCreateWithFlags(&sd2, cudaStreamNonBlocking);
    cudaEvent_t e0, e2, e3, e4;
    cudaEventCreateWithFlags(&e0, cudaEventDisableTiming);
    cudaEventCreateWithFlags(&e2, cudaEventDisableTiming);
    cudaEventCreateWithFlags(&e3, cudaEventDisableTiming);
    cudaEventCreateWithFlags(&e4, cudaEventDisableTiming);

    cudaEventRecord(e0, 0);
    cudaStreamWaitEvent(sd1, e0, 0);

    prep_kernel<<<12544, 256>>>(x);
    pack_wt<<<dim3(32, 32, 4), 256>>>(region_W, class_W, gat_W, 0);
    pack_wt<<<dim3(32, 32, 13), 256, 0, sd1>>>(region_W, class_W, gat_W, 4);
    cudaEventRecord(e3, sd1);

    gemm_h<<<dim3(4, 168, 4), 128, SMEM_DYN>>>(region_b, 21504, 0);
    hmean_kernel<<<dim3(1024, 4), 64>>>(region_gamma, region_beta);
    cudaEventRecord(e2, 0);

    cudaStreamWaitEvent(sd2, e2, 0);
    preds_kernel<<<1024, 256, 0, sd2>>>(upfc_W, upfc_b, midfc_W, midfc_b,
                                        d1fc_W, d1fc_b, d2fc_W, d2fc_b, out);
    cudaEventRecord(e4, sd2);

    cudaStreamWaitEvent(0, e3, 0);
    gemm_h<<<dim3(4, 168, 12), 128, SMEM_DYN>>>(class_b, 21504, 1);
    bn_y_kernel<<<dim3(1024, 12), 64>>>(class_gamma, class_beta);
    gemm_h<<<dim3(4, 96, 1), 128, SMEM_DYN>>>(nullptr, 12288, 2);
    gat_kernel<<<1024, 256>>>(adj_mask, gat_al, gat_ar);
    tconv_kernel<<<dim3(32, 12), 512>>>(tconv_W, tconv_b);
    tbn_kernel<<<dim3(1024, 12), 128>>>(tbn_gamma, tbn_beta, out);

    cudaStreamWaitEvent(0, e4, 0);

    cudaEventDestroy(e0);
    cudaEventDestroy(e2);
    cudaEventDestroy(e3);
    cudaEventDestroy(e4);
    cudaStreamDestroy(sd1);
    cudaStreamDestroy(sd2);
}